// round 6
// baseline (speedup 1.0000x reference)
#include <cuda_runtime.h>
#include <math.h>

// SSKernelNPLR: H=256, S=256 (rep=1), N=64, R=1, CH=1, L=2048
#define HH 256
#define NN 64
#define LL 2048

// Packed half-spectrum Z[h][k], k in [0,1024): irfft(X, 2048) == interleaved
// 1024-point complex IDFT of Z.
__device__ float2 g_Z[HH * 1024];

// ---- packed f32x2 helpers (sm_100+) ----
__device__ __forceinline__ unsigned long long pack2(float lo, float hi) {
    unsigned long long r;
    asm("mov.b64 %0, {%1, %2};" : "=l"(r) : "f"(lo), "f"(hi));
    return r;
}
__device__ __forceinline__ void unpack2(unsigned long long v, float& lo, float& hi) {
    asm("mov.b64 {%0, %1}, %2;" : "=f"(lo), "=f"(hi) : "l"(v));
}
__device__ __forceinline__ unsigned long long ffma2(
    unsigned long long a, unsigned long long b, unsigned long long c) {
    unsigned long long d;
    asm("fma.rn.f32x2 %0, %1, %2, %3;" : "=l"(d) : "l"(a), "l"(b), "l"(c));
    return d;
}
__device__ __forceinline__ float frcp_a(float x) {
    float r;
    asm("rcp.approx.f32 %0, %1;" : "=f"(r) : "f"(x));
    return r;
}

// ---------------------------------------------------------------------------
// Kernel 1: Cauchy + Woodbury + bilinear -> packed spectrum Z.
//
// Basis-function form (per n, slot s; u = y^2, t = 1/|d|^2, tu = t*u):
//   re_s += t*P_s + tu*Q_s      P = Nr*K1,  Q = vy*K2 - Nr
//   im_s += y*(t*R_s - tu*vy)   R = vy*K1 - Nr*K2
//   |d|^2 = (K1-u)^2 + K2^2*u   (stable sum-of-squares form)
// Accumulated packed: A_s += (P,Q)*(t,tu);  B_s += (R,-vy)*(t,tu)
// Epilogue: re = A.x+A.y ; im = y*(B.x+B.y)
//
// grid (HH, 5): by<4 main; t<128 -> lA = by*128+t, t>=128 -> 1024-lA
// (pair exchanged via smem, emits packed Z directly). by==4: l=512 self-pair.
// ---------------------------------------------------------------------------
__global__ void __launch_bounds__(256) cauchy_kernel(
    const float* __restrict__ Cin, const float* __restrict__ Bin,
    const float* __restrict__ Pin, const float* __restrict__ iwr,
    const float* __restrict__ wim, const float* __restrict__ logdt)
{
    __shared__ float2 sK[NN];        // (K1, K2^2)
    __shared__ float4 sP[4][NN];     // (P, Q, R, -vy) per slot
    __shared__ float2 sX[256];       // pair exchange

    const int h = blockIdx.x;
    const int tid = threadIdx.x;

    if (tid < NN) {
        const int n = tid;
        const int idx = h * NN + n;
        const float dt = expf(logdt[h]);
        const float a = -expf(iwr[idx]) * dt;
        const float b = wim[idx] * dt;
        const float K1 = fmaf(a, a, b * b);
        const float K2 = -2.0f * a;
        sK[n] = make_float2(K1, K2 * K2);

        const float Br = Bin[2*idx], Bi = Bin[2*idx+1];
        const float Cr = Cin[2*idx], Ci = Cin[2*idx+1];
        const float Pr = Pin[2*idx], Pi = Pin[2*idx+1];

        float p, q, Nr, vy;
        p = Br*Cr - Bi*Ci;  q = Br*Ci + Bi*Cr;               // v00 = B*C
        Nr = -2.0f*(p*a + q*b)*dt; vy = 2.0f*p*dt;
        sP[0][n] = make_float4(Nr*K1, vy*K2 - Nr, vy*K1 - Nr*K2, -vy);
        p = Br*Pr + Bi*Pi;  q = Bi*Pr - Br*Pi;               // v01 = B*conj(P)
        Nr = -2.0f*(p*a + q*b)*dt; vy = 2.0f*p*dt;
        sP[1][n] = make_float4(Nr*K1, vy*K2 - Nr, vy*K1 - Nr*K2, -vy);
        p = Pr*Cr - Pi*Ci;  q = Pr*Ci + Pi*Cr;               // v10 = P*C
        Nr = -2.0f*(p*a + q*b)*dt; vy = 2.0f*p*dt;
        sP[2][n] = make_float4(Nr*K1, vy*K2 - Nr, vy*K1 - Nr*K2, -vy);
        p = Pr*Pr + Pi*Pi;                                   // v11 = |P|^2
        Nr = -2.0f*p*a*dt; vy = 2.0f*p*dt;
        sP[3][n] = make_float4(Nr*K1, vy*K2 - Nr, vy*K1 - Nr*K2, -vy);
    }
    __syncthreads();

    const int by = blockIdx.y;
    const bool special = (by == 4);
    int l;
    if (special) {
        if (tid >= 32) return;       // one warp; no syncs below on this path
        l = 512;
    } else {
        const int tq = tid & 127;
        const int lA = by * 128 + tq;
        l = (tid < 128) ? lA : (1024 - lA);
    }

    float y = 2.0f * tanf((float)l * (3.14159265358979323846f / 2048.0f));
    y = fminf(fmaxf(y, -3.0e7f), 3.0e7f);     // guard l -> 1024 pole
    const float u = y * y;

    const ulonglong2* __restrict__ p0 = reinterpret_cast<const ulonglong2*>(sP[0]);
    const ulonglong2* __restrict__ p1 = reinterpret_cast<const ulonglong2*>(sP[1]);
    const ulonglong2* __restrict__ p2 = reinterpret_cast<const ulonglong2*>(sP[2]);
    const ulonglong2* __restrict__ p3 = reinterpret_cast<const ulonglong2*>(sP[3]);

    unsigned long long A0 = 0ull, B0 = 0ull, A1 = 0ull, B1 = 0ull;
    unsigned long long A2 = 0ull, B2 = 0ull, A3 = 0ull, B3 = 0ull;

    #pragma unroll 4
    for (int n = 0; n < NN; n++) {
        const float2 kk = sK[n];                      // (K1, K2^2)
        const float dr = kk.x - u;
        const float md = fmaf(dr, dr, kk.y * u);      // |d|^2, stable
        const float t  = frcp_a(md);
        const float tu = t * u;
        const unsigned long long T = pack2(t, tu);

        ulonglong2 q;
        q = p0[n]; A0 = ffma2(q.x, T, A0); B0 = ffma2(q.y, T, B0);
        q = p1[n]; A1 = ffma2(q.x, T, A1); B1 = ffma2(q.y, T, B1);
        q = p2[n]; A2 = ffma2(q.x, T, A2); B2 = ffma2(q.y, T, B2);
        q = p3[n]; A3 = ffma2(q.x, T, A3); B3 = ffma2(q.y, T, B3);
    }

    float ax, ay, bx, byy;
    float r0r, r0i, r1r, r1i, r2r, r2i, r3r, r3i;
    unpack2(A0, ax, ay); unpack2(B0, bx, byy);
    r0r = ax + ay;  r0i = y * (bx + byy);
    unpack2(A1, ax, ay); unpack2(B1, bx, byy);
    r1r = ax + ay;  r1i = y * (bx + byy);
    unpack2(A2, ax, ay); unpack2(B2, bx, byy);
    r2r = ax + ay;  r2i = y * (bx + byy);
    unpack2(A3, ax, ay); unpack2(B3, bx, byy);
    r3r = ax + ay;  r3i = y * (bx + byy);

    // Woodbury: kf = r00 - r01*r10/(1 + r11)
    const float dre  = 1.0f + r3r;
    const float dim_ = r3i;
    const float dm = frcp_a(fmaf(dre, dre, dim_ * dim_));
    const float tr = r1r * r2r - r1i * r2i;
    const float ti = r1r * r2i + r1i * r2r;
    const float wr = (tr * dre + ti * dim_) * dm;
    const float wi = (ti * dre - tr * dim_) * dm;
    const float kr = r0r - wr;
    const float ki = r0i - wi;

    // * 2/(1+omega) = (1 + i*y/2)
    const float hy = 0.5f * y;
    const float2 X = make_float2(kr - ki * hy, ki + kr * hy);

    float2* __restrict__ Z = &g_Z[h * 1024];

    if (special) {
        if (tid == 0)
            Z[512] = make_float2(X.x * (1.0f / 1024.0f), -X.y * (1.0f / 1024.0f));
        return;
    }

    sX[tid] = X;
    __syncthreads();

    if (tid < 128) {
        const int lA = by * 128 + tid;
        const float2 X1 = sX[tid + 128];      // X[1024 - lA]
        const float Sx = X.x + X1.x, Sy = X.y - X1.y;
        const float Dx = X.x - X1.x, Dy = X.y + X1.y;
        float ts, tc;
        sincospif((float)lA * (1.0f / 1024.0f), &ts, &tc);   // e^{i pi lA/1024}
        const float Tx = tc * Dx - ts * Dy;
        const float Ty = tc * Dy + ts * Dx;
        const float sc = 1.0f / 2048.0f;
        Z[lA] = make_float2((Sx - Ty) * sc, (Sy + Tx) * sc);
        if (lA != 0)
            Z[1024 - lA] = make_float2((Sx + Ty) * sc, (Tx - Sy) * sc);
    }
}

// ---------------------------------------------------------------------------
// Kernel 2: 1024-point complex IDFT of Z per h (two-step 32x32), m-split 4-way,
// table-based twiddles (all reduce mod 32 after fold):
//   A [k1][m] = sum_{k2<32} Z[k1+32k2] tw[(k2*m)&31]
//   A''[k1][m] = A[k1][m] * e^{2pi i k1 m/1024}      (fold, once per entry)
//   z[32q+m]  = sum_{k1<32} A''[k1][m] tw[(k1*q)&31]
//   out[2n] = Re z[n], out[2n+1] = Im z[n]
// ---------------------------------------------------------------------------
__global__ void __launch_bounds__(256) irfft_kernel(float* __restrict__ out)
{
    __shared__ float2 sA[32][8];    // 2 KB
    __shared__ float2 tw[32];       // e^{2pi i j/32}

    const int h = blockIdx.x;
    const int j = blockIdx.y;
    const int tid = threadIdx.x;
    const int m8 = tid & 7;
    const int r  = tid >> 3;        // [0,32)
    const int m  = j * 8 + m8;
    const float2* __restrict__ Z = &g_Z[h * 1024];

    if (tid < 32) {
        float s, c;
        sincospif((float)tid * (1.0f / 16.0f), &s, &c);
        tw[tid] = make_float2(c, s);
    }
    __syncthreads();

    // Step A: k1 = r; twiddle index walks (k2*m) mod 32
    {
        float ar = 0.0f, ai = 0.0f;
        int idx = 0;
        #pragma unroll 8
        for (int k2 = 0; k2 < 32; k2++) {
            const float2 x = Z[r + 32 * k2];
            const float2 w = tw[idx];
            ar = fmaf(x.x, w.x, fmaf(-x.y, w.y, ar));
            ai = fmaf(x.x, w.y, fmaf( x.y, w.x, ai));
            idx = (idx + m) & 31;
        }
        // fold twiddle e^{2pi i r*m/1024}
        float fs, fc;
        sincospif((float)(r * m) * (1.0f / 512.0f), &fs, &fc);
        sA[r][m8] = make_float2(ar * fc - ai * fs, ar * fs + ai * fc);
    }
    __syncthreads();

    // Step B: output n = 32*r + m; twiddle index walks (k1*r) mod 32
    {
        float zr = 0.0f, zi = 0.0f;
        int idx = 0;
        #pragma unroll 8
        for (int k1 = 0; k1 < 32; k1++) {
            const float2 a = sA[k1][m8];
            const float2 w = tw[idx];
            zr = fmaf(a.x, w.x, fmaf(-a.y, w.y, zr));
            zi = fmaf(a.x, w.y, fmaf( a.y, w.x, zi));
            idx = (idx + r) & 31;
        }
        reinterpret_cast<float2*>(out + h * LL)[(r << 5) + m] = make_float2(zr, zi);
    }
}

// ---------------------------------------------------------------------------
// Inputs: 0:C 1:B 2:P 3:inv_w_real 4:w_imag 5:log_dt 6:L(ignored)
// Output: (1, 256, 2048) f32
// ---------------------------------------------------------------------------
extern "C" void kernel_launch(void* const* d_in, const int* in_sizes, int n_in,
                              void* d_out, int out_size)
{
    const float* C     = (const float*)d_in[0];
    const float* B     = (const float*)d_in[1];
    const float* P     = (const float*)d_in[2];
    const float* iwr   = (const float*)d_in[3];
    const float* wimag = (const float*)d_in[4];
    const float* logdt = (const float*)d_in[5];
    float* out = (float*)d_out;

    cauchy_kernel<<<dim3(HH, 5), 256>>>(C, B, P, iwr, wimag, logdt);
    irfft_kernel<<<dim3(HH, 4), 256>>>(out);
}

// round 7
// speedup vs baseline: 1.0259x; 1.0259x over previous
#include <cuda_runtime.h>
#include <math.h>

// SSKernelNPLR: H=256, S=256 (rep=1), N=64, R=1, CH=1, L=2048
#define HH 256
#define NN 64
#define LL 2048

// Packed half-spectrum Z[h][k], k in [0,1024): irfft(X, 2048) == interleaved
// 1024-point complex IDFT of Z.
__device__ float2 g_Z[HH * 1024];

// ---- packed f32x2 helpers (sm_100+) ----
__device__ __forceinline__ unsigned long long pack2(float lo, float hi) {
    unsigned long long r;
    asm("mov.b64 %0, {%1, %2};" : "=l"(r) : "f"(lo), "f"(hi));
    return r;
}
__device__ __forceinline__ void unpack2(unsigned long long v, float& lo, float& hi) {
    asm("mov.b64 {%0, %1}, %2;" : "=f"(lo), "=f"(hi) : "l"(v));
}
__device__ __forceinline__ unsigned long long ffma2(
    unsigned long long a, unsigned long long b, unsigned long long c) {
    unsigned long long d;
    asm("fma.rn.f32x2 %0, %1, %2, %3;" : "=l"(d) : "l"(a), "l"(b), "l"(c));
    return d;
}
__device__ __forceinline__ float frcp_a(float x) {
    float r;
    asm("rcp.approx.f32 %0, %1;" : "=f"(r) : "f"(x));
    return r;
}

// ---------------------------------------------------------------------------
// Kernel 1: Cauchy + Woodbury + bilinear -> packed spectrum Z.
//
// Basis-function form (per n, slot s; u = y^2, t = 1/|d|^2, tu = t*u):
//   re_s += t*P_s + tu*Q_s      P = Nr*K1,  Q = vy*K2 - Nr
//   im_s += y*(t*R_s - tu*vy)   R = vy*K1 - Nr*K2
//   |d|^2 = (K1-u)^2 + K2^2*u   (stable sum-of-squares form)
// Accumulated packed: A_s += (P,Q)*(t,tu);  B_s += (R,-vy)*(t,tu)
// Epilogue: re = A.x+A.y ; im = y*(B.x+B.y)
//
// grid (HH, 5): by<4 main; t<128 -> lA = by*128+t, t>=128 -> 1024-lA
// (pair exchanged via smem, emits packed Z directly). by==4: l=512 self-pair.
// ---------------------------------------------------------------------------
__global__ void __launch_bounds__(256) cauchy_kernel(
    const float* __restrict__ Cin, const float* __restrict__ Bin,
    const float* __restrict__ Pin, const float* __restrict__ iwr,
    const float* __restrict__ wim, const float* __restrict__ logdt)
{
    __shared__ float2 sK[NN];        // (K1, K2^2)
    __shared__ float4 sP[4][NN];     // (P, Q, R, -vy) per slot
    __shared__ float2 sX[256];       // pair exchange

    const int h = blockIdx.x;
    const int tid = threadIdx.x;

    if (tid < NN) {
        const int n = tid;
        const int idx = h * NN + n;
        const float dt = expf(logdt[h]);
        const float a = -expf(iwr[idx]) * dt;
        const float b = wim[idx] * dt;
        const float K1 = fmaf(a, a, b * b);
        const float K2 = -2.0f * a;
        sK[n] = make_float2(K1, K2 * K2);

        const float Br = Bin[2*idx], Bi = Bin[2*idx+1];
        const float Cr = Cin[2*idx], Ci = Cin[2*idx+1];
        const float Pr = Pin[2*idx], Pi = Pin[2*idx+1];

        float p, q, Nr, vy;
        p = Br*Cr - Bi*Ci;  q = Br*Ci + Bi*Cr;               // v00 = B*C
        Nr = -2.0f*(p*a + q*b)*dt; vy = 2.0f*p*dt;
        sP[0][n] = make_float4(Nr*K1, vy*K2 - Nr, vy*K1 - Nr*K2, -vy);
        p = Br*Pr + Bi*Pi;  q = Bi*Pr - Br*Pi;               // v01 = B*conj(P)
        Nr = -2.0f*(p*a + q*b)*dt; vy = 2.0f*p*dt;
        sP[1][n] = make_float4(Nr*K1, vy*K2 - Nr, vy*K1 - Nr*K2, -vy);
        p = Pr*Cr - Pi*Ci;  q = Pr*Ci + Pi*Cr;               // v10 = P*C
        Nr = -2.0f*(p*a + q*b)*dt; vy = 2.0f*p*dt;
        sP[2][n] = make_float4(Nr*K1, vy*K2 - Nr, vy*K1 - Nr*K2, -vy);
        p = Pr*Pr + Pi*Pi;                                   // v11 = |P|^2
        Nr = -2.0f*p*a*dt; vy = 2.0f*p*dt;
        sP[3][n] = make_float4(Nr*K1, vy*K2 - Nr, vy*K1 - Nr*K2, -vy);
    }
    __syncthreads();

    const int by = blockIdx.y;
    const bool special = (by == 4);
    int l;
    if (special) {
        if (tid >= 32) return;       // one warp; no syncs below on this path
        l = 512;
    } else {
        const int tq = tid & 127;
        const int lA = by * 128 + tq;
        l = (tid < 128) ? lA : (1024 - lA);
    }

    float y = 2.0f * tanf((float)l * (3.14159265358979323846f / 2048.0f));
    y = fminf(fmaxf(y, -3.0e7f), 3.0e7f);     // guard l -> 1024 pole
    const float u = y * y;

    const ulonglong2* __restrict__ p0 = reinterpret_cast<const ulonglong2*>(sP[0]);
    const ulonglong2* __restrict__ p1 = reinterpret_cast<const ulonglong2*>(sP[1]);
    const ulonglong2* __restrict__ p2 = reinterpret_cast<const ulonglong2*>(sP[2]);
    const ulonglong2* __restrict__ p3 = reinterpret_cast<const ulonglong2*>(sP[3]);

    unsigned long long A0 = 0ull, B0 = 0ull, A1 = 0ull, B1 = 0ull;
    unsigned long long A2 = 0ull, B2 = 0ull, A3 = 0ull, B3 = 0ull;

    #pragma unroll 4
    for (int n = 0; n < NN; n++) {
        const float2 kk = sK[n];                      // (K1, K2^2)
        const float dr = kk.x - u;
        const float md = fmaf(dr, dr, kk.y * u);      // |d|^2, stable
        const float t  = frcp_a(md);
        const float tu = t * u;
        const unsigned long long T = pack2(t, tu);

        ulonglong2 q;
        q = p0[n]; A0 = ffma2(q.x, T, A0); B0 = ffma2(q.y, T, B0);
        q = p1[n]; A1 = ffma2(q.x, T, A1); B1 = ffma2(q.y, T, B1);
        q = p2[n]; A2 = ffma2(q.x, T, A2); B2 = ffma2(q.y, T, B2);
        q = p3[n]; A3 = ffma2(q.x, T, A3); B3 = ffma2(q.y, T, B3);
    }

    float ax, ay, bx, byy;
    float r0r, r0i, r1r, r1i, r2r, r2i, r3r, r3i;
    unpack2(A0, ax, ay); unpack2(B0, bx, byy);
    r0r = ax + ay;  r0i = y * (bx + byy);
    unpack2(A1, ax, ay); unpack2(B1, bx, byy);
    r1r = ax + ay;  r1i = y * (bx + byy);
    unpack2(A2, ax, ay); unpack2(B2, bx, byy);
    r2r = ax + ay;  r2i = y * (bx + byy);
    unpack2(A3, ax, ay); unpack2(B3, bx, byy);
    r3r = ax + ay;  r3i = y * (bx + byy);

    // Woodbury: kf = r00 - r01*r10/(1 + r11)
    const float dre  = 1.0f + r3r;
    const float dim_ = r3i;
    const float dm = frcp_a(fmaf(dre, dre, dim_ * dim_));
    const float tr = r1r * r2r - r1i * r2i;
    const float ti = r1r * r2i + r1i * r2r;
    const float wr = (tr * dre + ti * dim_) * dm;
    const float wi = (ti * dre - tr * dim_) * dm;
    const float kr = r0r - wr;
    const float ki = r0i - wi;

    // * 2/(1+omega) = (1 + i*y/2)
    const float hy = 0.5f * y;
    const float2 X = make_float2(kr - ki * hy, ki + kr * hy);

    float2* __restrict__ Z = &g_Z[h * 1024];

    if (special) {
        if (tid == 0)
            Z[512] = make_float2(X.x * (1.0f / 1024.0f), -X.y * (1.0f / 1024.0f));
        return;
    }

    sX[tid] = X;
    __syncthreads();

    if (tid < 128) {
        const int lA = by * 128 + tid;
        const float2 X1 = sX[tid + 128];      // X[1024 - lA]
        const float Sx = X.x + X1.x, Sy = X.y - X1.y;
        const float Dx = X.x - X1.x, Dy = X.y + X1.y;
        float ts, tc;
        sincospif((float)lA * (1.0f / 1024.0f), &ts, &tc);   // e^{i pi lA/1024}
        const float Tx = tc * Dx - ts * Dy;
        const float Ty = tc * Dy + ts * Dx;
        const float sc = 1.0f / 2048.0f;
        Z[lA] = make_float2((Sx - Ty) * sc, (Sy + Tx) * sc);
        if (lA != 0)
            Z[1024 - lA] = make_float2((Sx + Ty) * sc, (Tx - Sy) * sc);
    }
}

// ---------------------------------------------------------------------------
// Kernel 2: 1024-point complex IDFT of Z per h (two-step 32x32), m-split 4-way,
// table-based twiddles (all reduce mod 32 after fold):
//   A [k1][m] = sum_{k2<32} Z[k1+32k2] tw[(k2*m)&31]
//   A''[k1][m] = A[k1][m] * e^{2pi i k1 m/1024}      (fold, once per entry)
//   z[32q+m]  = sum_{k1<32} A''[k1][m] tw[(k1*q)&31]
//   out[2n] = Re z[n], out[2n+1] = Im z[n]
// ---------------------------------------------------------------------------
__global__ void __launch_bounds__(256) irfft_kernel(float* __restrict__ out)
{
    __shared__ float2 sA[32][8];    // 2 KB
    __shared__ float2 tw[32];       // e^{2pi i j/32}

    const int h = blockIdx.x;
    const int j = blockIdx.y;
    const int tid = threadIdx.x;
    const int m8 = tid & 7;
    const int r  = tid >> 3;        // [0,32)
    const int m  = j * 8 + m8;
    const float2* __restrict__ Z = &g_Z[h * 1024];

    if (tid < 32) {
        float s, c;
        sincospif((float)tid * (1.0f / 16.0f), &s, &c);
        tw[tid] = make_float2(c, s);
    }
    __syncthreads();

    // Step A: k1 = r; twiddle index walks (k2*m) mod 32
    {
        float ar = 0.0f, ai = 0.0f;
        int idx = 0;
        #pragma unroll 8
        for (int k2 = 0; k2 < 32; k2++) {
            const float2 x = Z[r + 32 * k2];
            const float2 w = tw[idx];
            ar = fmaf(x.x, w.x, fmaf(-x.y, w.y, ar));
            ai = fmaf(x.x, w.y, fmaf( x.y, w.x, ai));
            idx = (idx + m) & 31;
        }
        // fold twiddle e^{2pi i r*m/1024}
        float fs, fc;
        sincospif((float)(r * m) * (1.0f / 512.0f), &fs, &fc);
        sA[r][m8] = make_float2(ar * fc - ai * fs, ar * fs + ai * fc);
    }
    __syncthreads();

    // Step B: output n = 32*r + m; twiddle index walks (k1*r) mod 32
    {
        float zr = 0.0f, zi = 0.0f;
        int idx = 0;
        #pragma unroll 8
        for (int k1 = 0; k1 < 32; k1++) {
            const float2 a = sA[k1][m8];
            const float2 w = tw[idx];
            zr = fmaf(a.x, w.x, fmaf(-a.y, w.y, zr));
            zi = fmaf(a.x, w.y, fmaf( a.y, w.x, zi));
            idx = (idx + r) & 31;
        }
        reinterpret_cast<float2*>(out + h * LL)[(r << 5) + m] = make_float2(zr, zi);
    }
}

// ---------------------------------------------------------------------------
// Inputs: 0:C 1:B 2:P 3:inv_w_real 4:w_imag 5:log_dt 6:L(ignored)
// Output: (1, 256, 2048) f32
// ---------------------------------------------------------------------------
extern "C" void kernel_launch(void* const* d_in, const int* in_sizes, int n_in,
                              void* d_out, int out_size)
{
    const float* C     = (const float*)d_in[0];
    const float* B     = (const float*)d_in[1];
    const float* P     = (const float*)d_in[2];
    const float* iwr   = (const float*)d_in[3];
    const float* wimag = (const float*)d_in[4];
    const float* logdt = (const float*)d_in[5];
    float* out = (float*)d_out;

    cauchy_kernel<<<dim3(HH, 5), 256>>>(C, B, P, iwr, wimag, logdt);
    irfft_kernel<<<dim3(HH, 4), 256>>>(out);
}